// round 10
// baseline (speedup 1.0000x reference)
#include <cuda_runtime.h>

// DySample fused (one kernel): B=16, C=64, H=W=128, scale=2, groups=4
// Phase 1 (block = one (b,h) row): off = (x . w_off^T + b_off)*0.25 + init -> smem
//   Lane map: thread = pixel (tid&127) x och-half (tid>>7). Each warp's x load
//   is 32 consecutive floats = 1 wavefront, no redundancy; weights broadcast LDS.
// Phase 2: out[b, g*16+cc, 2h+ri, 2w+rj] = bilinear(x[b,g*16+cc], iy, ix)
//   init sign s = (g&1)? ri : rj  =>  tap window = s-diagonal 2x2 of the
//   3x3 neighborhood; 7 loaded values serve all 4 positions per channel.
//   Bilinear as nested lerps (state = wx, wy per position).
//   Cold exact-repair loop handles positions escaping the predicted window.

#define HW 16384

__device__ __forceinline__ unsigned long long pack2(float a, float b) {
    unsigned long long r;
    asm("mov.b64 %0, {%1, %2};" : "=l"(r) : "f"(a), "f"(b));
    return r;
}
__device__ __forceinline__ void ffma2(unsigned long long& d,
                                      unsigned long long a, unsigned long long b) {
    asm("fma.rn.f32x2 %0, %1, %2, %0;" : "+l"(d) : "l"(a), "l"(b));
}
__device__ __forceinline__ float2 unpack2(unsigned long long v) {
    float2 f;
    asm("mov.b64 {%0, %1}, %2;" : "=f"(f.x), "=f"(f.y) : "l"(v));
    return f;
}
__device__ __forceinline__ float clampf(float v, float lo, float hi) {
    return fminf(fmaxf(v, lo), hi);
}

__global__ __launch_bounds__(256, 5) void dysample_fused(
    const float* __restrict__ x,
    const float* __restrict__ w_off,
    const float* __restrict__ b_off,
    float* __restrict__ out)
{
    __shared__ __align__(16) float ws[64 * 32];     // [c][o]
    __shared__ __align__(16) float offs[32 * 128];  // [o][w]

    const int h   = blockIdx.x;
    const int b   = blockIdx.y;
    const int tid = threadIdx.x;

    // Stage weights transposed (8 KB, L2-hot after first wave).
    for (int i = tid; i < 2048; i += 256) {
        int c = i >> 5, o = i & 31;
        ws[i] = __ldg(&w_off[o * 64 + c]);
    }
    __syncthreads();

    // ---------------- Phase 1: 64->32 matvec for this row (packed f32x2) ----
    {
        const int px   = tid & 127;      // one pixel per thread, coalesced
        const int half = tid >> 7;       // 16 out-channels per thread
        const float* xb = x + ((b * 64) << 14) + (h << 7) + px;

        unsigned long long acc[8];       // 8 och-pairs = 16 channels
        #pragma unroll
        for (int i = 0; i < 8; i++) acc[i] = 0ull;

        #pragma unroll 4
        for (int c = 0; c < 64; c++) {
            const float xv = __ldg(xb + (c << 14));
            const unsigned long long xp = pack2(xv, xv);
            const ulonglong2* wq =
                reinterpret_cast<const ulonglong2*>(&ws[c * 32 + (half << 4)]);
            const ulonglong2 wA = wq[0], wB = wq[1], wC = wq[2], wD = wq[3];
            ffma2(acc[0], xp, wA.x); ffma2(acc[1], xp, wA.y);
            ffma2(acc[2], xp, wB.x); ffma2(acc[3], xp, wB.y);
            ffma2(acc[4], xp, wC.x); ffma2(acc[5], xp, wC.y);
            ffma2(acc[6], xp, wD.x); ffma2(acc[7], xp, wD.y);
        }

        #pragma unroll
        for (int i = 0; i < 8; i++) {
            const float2 f = unpack2(acc[i]);
            #pragma unroll
            for (int e = 0; e < 2; e++) {
                const int o = (half << 4) + (i << 1) + e;
                const float bias = __ldg(&b_off[o]);
                const int dd = (o >> 2) & 1, ii = (o >> 1) & 1, jj = o & 1;
                const float initv = 0.25f * (float)((((dd ? ii : jj) << 1)) - 1);
                const float a = e ? f.y : f.x;
                offs[(o << 7) + px] = (a + bias) * 0.25f + initv;
            }
        }
    }
    __syncthreads();

    // ---------------- Phase 2: bilinear sampling --------------------------
    const int w = tid & 127;
    const int z = tid >> 7;
    const float fw = (float)w, fh = (float)h;
    const int wm = max(w - 1, 0), wp = min(w + 1, 127);
    const int hm = max(h - 1, 0), hp = min(h + 1, 127);
    const int rm = hm << 7, rc = h << 7, rp = hp << 7;

    for (int gpair = 0; gpair < 2; gpair++) {
        #pragma unroll
        for (int gg = 0; gg < 2; gg++) {        // compile-time parity
            const int g = gpair * 2 + gg;

            float WX[4], WY[4];
            int bad = 0;
            #pragma unroll
            for (int pos = 0; pos < 4; pos++) {  // pos = ri*2 + rj
                const int ri = pos >> 1, rj = pos & 1;
                const int s = gg ? ri : rj;      // compile-time
                const int o = (g << 2) + pos;
                const float offx = offs[(o << 7) + w];
                const float offy = offs[((o + 16) << 7) + w];
                const float ix = clampf(fw + offx, 0.0f, 127.0f);
                const float iy = clampf(fh + offy, 0.0f, 127.0f);
                const float x0f = floorf(ix), y0f = floorf(iy);
                const float wx = ix - x0f, wy = iy - y0f;
                const int x0 = (int)x0f, y0 = (int)y0f;
                const int x1 = min(x0 + 1, 127), y1 = min(y0 + 1, 127);
                const int cx0 = s ? w : wm,  cx1 = s ? wp : w;
                const int cy0 = s ? h : hm,  cy1 = s ? hp : h;
                // Exact iff column-0/row-0 taps match; mismatched col-1/row-1
                // taps carry zero weight when wx/wy == 0.
                const bool ok = (x0 == cx0) && (wx == 0.0f || x1 == cx1)
                             && (y0 == cy0) && (wy == 0.0f || y1 == cy1);
                if (!ok) bad |= (1 << pos);
                WX[pos] = wx;
                WY[pos] = wy;
            }

            const int cbase = b * 64 + (g << 4) + (z << 3);
            const float* pb = x + (cbase << 14);
            float* db = out + (cbase << 16) + (h << 9) + (w << 1);

            {   // fast path: 7 taps serve 4 outputs per channel (nested lerps)
                const float* p = pb;
                float* dst = db;
                #pragma unroll 2
                for (int cc = 0; cc < 8; cc++) {
                    const float r00 = __ldg(p + rm + wm), r01 = __ldg(p + rm + w);
                    const float r10 = __ldg(p + rc + wm), r11 = __ldg(p + rc + w);
                    const float r12 = __ldg(p + rc + wp);
                    const float r21 = __ldg(p + rp + w),  r22 = __ldg(p + rp + wp);
                    float v[4];
                    #pragma unroll
                    for (int pos = 0; pos < 4; pos++) {
                        const int s = gg ? (pos >> 1) : (pos & 1);  // compile-time
                        const float t00 = s ? r11 : r00, t01 = s ? r12 : r01;
                        const float t10 = s ? r21 : r10, t11 = s ? r22 : r11;
                        const float h0 = fmaf(WX[pos], t01 - t00, t00);
                        const float h1 = fmaf(WX[pos], t11 - t10, t10);
                        v[pos] = fmaf(WY[pos], h1 - h0, h0);
                    }
                    *reinterpret_cast<float2*>(dst)       = make_float2(v[0], v[1]);
                    *reinterpret_cast<float2*>(dst + 256) = make_float2(v[2], v[3]);
                    p += HW;
                    dst += 65536;
                }
            }

            if (bad) {  // cold exact repair (offset escaped predicted window)
                for (int pos = 0; pos < 4; pos++) {
                    if (!(bad & (1 << pos))) continue;
                    const int o = (g << 2) + pos;
                    const float offx = offs[(o << 7) + w];
                    const float offy = offs[((o + 16) << 7) + w];
                    const float ix = clampf(fw + offx, 0.0f, 127.0f);
                    const float iy = clampf(fh + offy, 0.0f, 127.0f);
                    const float x0f = floorf(ix), y0f = floorf(iy);
                    const float wx = ix - x0f, wy = iy - y0f;
                    const int x0 = (int)x0f, y0 = (int)y0f;
                    const int x1 = min(x0 + 1, 127), y1 = min(y0 + 1, 127);
                    const float* p = pb;
                    float* dst = db + (pos >> 1) * 256 + (pos & 1);
                    for (int cc = 0; cc < 8; cc++) {
                        const float u00 = __ldg(p + (y0 << 7) + x0);
                        const float u01 = __ldg(p + (y0 << 7) + x1);
                        const float u10 = __ldg(p + (y1 << 7) + x0);
                        const float u11 = __ldg(p + (y1 << 7) + x1);
                        *dst = (1.0f - wy) * ((1.0f - wx) * u00 + wx * u01)
                             + wy * ((1.0f - wx) * u10 + wx * u11);
                        p += HW;
                        dst += 65536;
                    }
                }
            }
        }
    }
}

extern "C" void kernel_launch(void* const* d_in, const int* in_sizes, int n_in,
                              void* d_out, int out_size)
{
    const float* x     = (const float*)d_in[0];  // [16,64,128,128]
    const float* w_off = (const float*)d_in[1];  // [32,64]
    const float* b_off = (const float*)d_in[2];  // [32]
    float* out = (float*)d_out;                  // [16,64,256,256]

    dysample_fused<<<dim3(128, 16), 256>>>(x, w_off, b_off, out);
    (void)in_sizes; (void)n_in; (void)out_size;
}

// round 11
// speedup vs baseline: 1.0652x; 1.0652x over previous
#include <cuda_runtime.h>

// DySample fused (one kernel): B=16, C=64, H=W=128, scale=2, groups=4
// Phase 1 (block = one (b,h) row): off = (x . w_off^T + b_off)*0.25 + init -> smem
//   Lane map (G=4 optimum of 4G + 64/G wavefronts/c): thread = 2 consecutive
//   pixels (tid&63) x 8 och (tid>>6). x via LDG.64 fully coalesced, weights via
//   2 broadcast LDS.128 (och-group warp-uniform).
// Phase 2: out[b, g*16+cc, 2h+ri, 2w+rj] = bilinear(x[b,g*16+cc], iy, ix)
//   init sign s = (g&1)? ri : rj  =>  tap window = s-diagonal 2x2 of the
//   3x3 neighborhood; 7 loaded values serve all 4 positions per channel.
//   Bilinear as nested lerps (state = wx, wy per position).
//   Cold exact-repair loop handles positions escaping the predicted window.

#define HW 16384

__device__ __forceinline__ unsigned long long pack2(float a, float b) {
    unsigned long long r;
    asm("mov.b64 %0, {%1, %2};" : "=l"(r) : "f"(a), "f"(b));
    return r;
}
__device__ __forceinline__ void ffma2(unsigned long long& d,
                                      unsigned long long a, unsigned long long b) {
    asm("fma.rn.f32x2 %0, %1, %2, %0;" : "+l"(d) : "l"(a), "l"(b));
}
__device__ __forceinline__ float2 unpack2(unsigned long long v) {
    float2 f;
    asm("mov.b64 {%0, %1}, %2;" : "=f"(f.x), "=f"(f.y) : "l"(v));
    return f;
}
__device__ __forceinline__ float clampf(float v, float lo, float hi) {
    return fminf(fmaxf(v, lo), hi);
}

__global__ __launch_bounds__(256, 5) void dysample_fused(
    const float* __restrict__ x,
    const float* __restrict__ w_off,
    const float* __restrict__ b_off,
    float* __restrict__ out)
{
    __shared__ __align__(16) float ws[64 * 32];     // [c][o]
    __shared__ __align__(16) float offs[32 * 128];  // [o][w]

    const int h   = blockIdx.x;
    const int b   = blockIdx.y;
    const int tid = threadIdx.x;

    // Stage weights transposed (8 KB, L2-hot after first wave).
    for (int i = tid; i < 2048; i += 256) {
        int c = i >> 5, o = i & 31;
        ws[i] = __ldg(&w_off[o * 64 + c]);
    }
    __syncthreads();

    // ---------------- Phase 1: 64->32 matvec for this row (packed f32x2) ----
    {
        const int pg = tid & 63;         // pixel pair: pixels 2pg, 2pg+1
        const int og = tid >> 6;         // och group: 8 och [8og, 8og+8)
        const int p0 = pg << 1;
        const float* xb = x + ((b * 64) << 14) + (h << 7) + p0;

        unsigned long long acc[2][4];    // [pixel][och-pair]
        #pragma unroll
        for (int p = 0; p < 2; p++)
            #pragma unroll
            for (int j = 0; j < 4; j++) acc[p][j] = 0ull;

        #pragma unroll 4
        for (int c = 0; c < 64; c++) {
            const float2 xv = __ldg(reinterpret_cast<const float2*>(xb + (c << 14)));
            const ulonglong2* wq =
                reinterpret_cast<const ulonglong2*>(&ws[c * 32 + (og << 3)]);
            const ulonglong2 wA = wq[0], wB = wq[1];
            const unsigned long long xp0 = pack2(xv.x, xv.x);
            const unsigned long long xp1 = pack2(xv.y, xv.y);
            ffma2(acc[0][0], xp0, wA.x); ffma2(acc[0][1], xp0, wA.y);
            ffma2(acc[0][2], xp0, wB.x); ffma2(acc[0][3], xp0, wB.y);
            ffma2(acc[1][0], xp1, wA.x); ffma2(acc[1][1], xp1, wA.y);
            ffma2(acc[1][2], xp1, wB.x); ffma2(acc[1][3], xp1, wB.y);
        }

        #pragma unroll
        for (int j = 0; j < 4; j++) {
            const float2 f0 = unpack2(acc[0][j]);   // pixel p0,   och 2j / 2j+1
            const float2 f1 = unpack2(acc[1][j]);   // pixel p0+1
            #pragma unroll
            for (int e = 0; e < 2; e++) {
                const int o = (og << 3) + (j << 1) + e;
                const float bias = __ldg(&b_off[o]);
                const int dd = (o >> 2) & 1, ii = (o >> 1) & 1, jj = o & 1;
                const float initv = 0.25f * (float)((((dd ? ii : jj) << 1)) - 1);
                float2 v;
                v.x = ((e ? f0.y : f0.x) + bias) * 0.25f + initv;
                v.y = ((e ? f1.y : f1.x) + bias) * 0.25f + initv;
                *reinterpret_cast<float2*>(&offs[(o << 7) + p0]) = v;
            }
        }
    }
    __syncthreads();

    // ---------------- Phase 2: bilinear sampling --------------------------
    const int w = tid & 127;
    const int z = tid >> 7;
    const float fw = (float)w, fh = (float)h;
    const int wm = max(w - 1, 0), wp = min(w + 1, 127);
    const int hm = max(h - 1, 0), hp = min(h + 1, 127);
    const int rm = hm << 7, rc = h << 7, rp = hp << 7;

    for (int gpair = 0; gpair < 2; gpair++) {
        #pragma unroll
        for (int gg = 0; gg < 2; gg++) {        // compile-time parity
            const int g = gpair * 2 + gg;

            float WX[4], WY[4];
            int bad = 0;
            #pragma unroll
            for (int pos = 0; pos < 4; pos++) {  // pos = ri*2 + rj
                const int ri = pos >> 1, rj = pos & 1;
                const int s = gg ? ri : rj;      // compile-time
                const int o = (g << 2) + pos;
                const float offx = offs[(o << 7) + w];
                const float offy = offs[((o + 16) << 7) + w];
                const float ix = clampf(fw + offx, 0.0f, 127.0f);
                const float iy = clampf(fh + offy, 0.0f, 127.0f);
                const float x0f = floorf(ix), y0f = floorf(iy);
                const float wx = ix - x0f, wy = iy - y0f;
                const int x0 = (int)x0f, y0 = (int)y0f;
                const int x1 = min(x0 + 1, 127), y1 = min(y0 + 1, 127);
                const int cx0 = s ? w : wm,  cx1 = s ? wp : w;
                const int cy0 = s ? h : hm,  cy1 = s ? hp : h;
                // Exact iff column-0/row-0 taps match; mismatched col-1/row-1
                // taps carry zero weight when wx/wy == 0.
                const bool ok = (x0 == cx0) && (wx == 0.0f || x1 == cx1)
                             && (y0 == cy0) && (wy == 0.0f || y1 == cy1);
                if (!ok) bad |= (1 << pos);
                WX[pos] = wx;
                WY[pos] = wy;
            }

            const int cbase = b * 64 + (g << 4) + (z << 3);
            const float* pb = x + (cbase << 14);
            float* db = out + (cbase << 16) + (h << 9) + (w << 1);

            {   // fast path: 7 taps serve 4 outputs per channel (nested lerps)
                const float* p = pb;
                float* dst = db;
                #pragma unroll 2
                for (int cc = 0; cc < 8; cc++) {
                    const float r00 = __ldg(p + rm + wm), r01 = __ldg(p + rm + w);
                    const float r10 = __ldg(p + rc + wm), r11 = __ldg(p + rc + w);
                    const float r12 = __ldg(p + rc + wp);
                    const float r21 = __ldg(p + rp + w),  r22 = __ldg(p + rp + wp);
                    float v[4];
                    #pragma unroll
                    for (int pos = 0; pos < 4; pos++) {
                        const int s = gg ? (pos >> 1) : (pos & 1);  // compile-time
                        const float t00 = s ? r11 : r00, t01 = s ? r12 : r01;
                        const float t10 = s ? r21 : r10, t11 = s ? r22 : r11;
                        const float h0 = fmaf(WX[pos], t01 - t00, t00);
                        const float h1 = fmaf(WX[pos], t11 - t10, t10);
                        v[pos] = fmaf(WY[pos], h1 - h0, h0);
                    }
                    *reinterpret_cast<float2*>(dst)       = make_float2(v[0], v[1]);
                    *reinterpret_cast<float2*>(dst + 256) = make_float2(v[2], v[3]);
                    p += HW;
                    dst += 65536;
                }
            }

            if (bad) {  // cold exact repair (offset escaped predicted window)
                for (int pos = 0; pos < 4; pos++) {
                    if (!(bad & (1 << pos))) continue;
                    const int o = (g << 2) + pos;
                    const float offx = offs[(o << 7) + w];
                    const float offy = offs[((o + 16) << 7) + w];
                    const float ix = clampf(fw + offx, 0.0f, 127.0f);
                    const float iy = clampf(fh + offy, 0.0f, 127.0f);
                    const float x0f = floorf(ix), y0f = floorf(iy);
                    const float wx = ix - x0f, wy = iy - y0f;
                    const int x0 = (int)x0f, y0 = (int)y0f;
                    const int x1 = min(x0 + 1, 127), y1 = min(y0 + 1, 127);
                    const float* p = pb;
                    float* dst = db + (pos >> 1) * 256 + (pos & 1);
                    for (int cc = 0; cc < 8; cc++) {
                        const float u00 = __ldg(p + (y0 << 7) + x0);
                        const float u01 = __ldg(p + (y0 << 7) + x1);
                        const float u10 = __ldg(p + (y1 << 7) + x0);
                        const float u11 = __ldg(p + (y1 << 7) + x1);
                        *dst = (1.0f - wy) * ((1.0f - wx) * u00 + wx * u01)
                             + wy * ((1.0f - wx) * u10 + wx * u11);
                        p += HW;
                        dst += 65536;
                    }
                }
            }
        }
    }
}

extern "C" void kernel_launch(void* const* d_in, const int* in_sizes, int n_in,
                              void* d_out, int out_size)
{
    const float* x     = (const float*)d_in[0];  // [16,64,128,128]
    const float* w_off = (const float*)d_in[1];  // [32,64]
    const float* b_off = (const float*)d_in[2];  // [32]
    float* out = (float*)d_out;                  // [16,64,256,256]

    dysample_fused<<<dim3(128, 16), 256>>>(x, w_off, b_off, out);
    (void)in_sizes; (void)n_in; (void)out_size;
}

// round 12
// speedup vs baseline: 1.1568x; 1.0860x over previous
#include <cuda_runtime.h>

// DySample fused (one kernel): B=16, C=64, H=W=128, scale=2, groups=4
// Phase 1 (block = one (b,h) row): off = (x . w_off^T + b_off)*0.25 + init -> smem
//   Lane map (G=4 optimum of 4G + 64/G wavefronts/c): thread = 2 consecutive
//   pixels (tid&63) x 8 och (tid>>6). x via LDG.64 fully coalesced, weights via
//   2 broadcast LDS.128 (och-group warp-uniform).
// Phase 2: thread = (w, z); z selects group-pair, thread covers 16 channels of
//   each of its 2 groups -> position setup runs 8x per thread (not 16x).
//   init sign s = (g&1)? ri : rj  =>  tap window = s-diagonal 2x2 of the
//   3x3 neighborhood; 7 loaded values serve all 4 positions per channel.
//   Bilinear as nested lerps; outputs stored with .cs (evict-first).
//   Cold exact-repair loop handles positions escaping the predicted window.

#define HW 16384

__device__ __forceinline__ unsigned long long pack2(float a, float b) {
    unsigned long long r;
    asm("mov.b64 %0, {%1, %2};" : "=l"(r) : "f"(a), "f"(b));
    return r;
}
__device__ __forceinline__ void ffma2(unsigned long long& d,
                                      unsigned long long a, unsigned long long b) {
    asm("fma.rn.f32x2 %0, %1, %2, %0;" : "+l"(d) : "l"(a), "l"(b));
}
__device__ __forceinline__ float2 unpack2(unsigned long long v) {
    float2 f;
    asm("mov.b64 {%0, %1}, %2;" : "=f"(f.x), "=f"(f.y) : "l"(v));
    return f;
}
__device__ __forceinline__ float clampf(float v, float lo, float hi) {
    return fminf(fmaxf(v, lo), hi);
}
__device__ __forceinline__ void stcs2(float* p, float a, float b) {
    asm volatile("st.global.cs.v2.f32 [%0], {%1, %2};"
                 :: "l"(p), "f"(a), "f"(b) : "memory");
}

__global__ __launch_bounds__(256, 5) void dysample_fused(
    const float* __restrict__ x,
    const float* __restrict__ w_off,
    const float* __restrict__ b_off,
    float* __restrict__ out)
{
    __shared__ __align__(16) float ws[64 * 32];     // [c][o]
    __shared__ __align__(16) float offs[32 * 128];  // [o][w]

    const int h   = blockIdx.x;
    const int b   = blockIdx.y;
    const int tid = threadIdx.x;

    // Stage weights transposed (8 KB, L2-hot after first wave).
    for (int i = tid; i < 2048; i += 256) {
        int c = i >> 5, o = i & 31;
        ws[i] = __ldg(&w_off[o * 64 + c]);
    }
    __syncthreads();

    // ---------------- Phase 1: 64->32 matvec for this row (packed f32x2) ----
    {
        const int pg = tid & 63;         // pixel pair: pixels 2pg, 2pg+1
        const int og = tid >> 6;         // och group: 8 och [8og, 8og+8)
        const int p0 = pg << 1;
        const float* xb = x + ((b * 64) << 14) + (h << 7) + p0;

        unsigned long long acc[2][4];    // [pixel][och-pair]
        #pragma unroll
        for (int p = 0; p < 2; p++)
            #pragma unroll
            for (int j = 0; j < 4; j++) acc[p][j] = 0ull;

        #pragma unroll 4
        for (int c = 0; c < 64; c++) {
            const float2 xv = __ldg(reinterpret_cast<const float2*>(xb + (c << 14)));
            const ulonglong2* wq =
                reinterpret_cast<const ulonglong2*>(&ws[c * 32 + (og << 3)]);
            const ulonglong2 wA = wq[0], wB = wq[1];
            const unsigned long long xp0 = pack2(xv.x, xv.x);
            const unsigned long long xp1 = pack2(xv.y, xv.y);
            ffma2(acc[0][0], xp0, wA.x); ffma2(acc[0][1], xp0, wA.y);
            ffma2(acc[0][2], xp0, wB.x); ffma2(acc[0][3], xp0, wB.y);
            ffma2(acc[1][0], xp1, wA.x); ffma2(acc[1][1], xp1, wA.y);
            ffma2(acc[1][2], xp1, wB.x); ffma2(acc[1][3], xp1, wB.y);
        }

        #pragma unroll
        for (int j = 0; j < 4; j++) {
            const float2 f0 = unpack2(acc[0][j]);   // pixel p0,   och 2j / 2j+1
            const float2 f1 = unpack2(acc[1][j]);   // pixel p0+1
            #pragma unroll
            for (int e = 0; e < 2; e++) {
                const int o = (og << 3) + (j << 1) + e;
                const float bias = __ldg(&b_off[o]);
                const int dd = (o >> 2) & 1, ii = (o >> 1) & 1, jj = o & 1;
                const float initv = 0.25f * (float)((((dd ? ii : jj) << 1)) - 1);
                float2 v;
                v.x = ((e ? f0.y : f0.x) + bias) * 0.25f + initv;
                v.y = ((e ? f1.y : f1.x) + bias) * 0.25f + initv;
                *reinterpret_cast<float2*>(&offs[(o << 7) + p0]) = v;
            }
        }
    }
    __syncthreads();

    // ---------------- Phase 2: bilinear sampling --------------------------
    const int w = tid & 127;
    const int z = tid >> 7;              // group-pair selector
    const float fw = (float)w, fh = (float)h;
    const int wm = max(w - 1, 0), wp = min(w + 1, 127);
    const int hm = max(h - 1, 0), hp = min(h + 1, 127);
    const int rm = hm << 7, rc = h << 7, rp = hp << 7;

    #pragma unroll
    for (int gg = 0; gg < 2; gg++) {        // compile-time parity
        const int g = (z << 1) + gg;        // g & 1 == gg

        float WX[4], WY[4];
        int bad = 0;
        #pragma unroll
        for (int pos = 0; pos < 4; pos++) {  // pos = ri*2 + rj
            const int ri = pos >> 1, rj = pos & 1;
            const int s = gg ? ri : rj;      // compile-time
            const int o = (g << 2) + pos;
            const float offx = offs[(o << 7) + w];
            const float offy = offs[((o + 16) << 7) + w];
            const float ix = clampf(fw + offx, 0.0f, 127.0f);
            const float iy = clampf(fh + offy, 0.0f, 127.0f);
            const float x0f = floorf(ix), y0f = floorf(iy);
            const float wx = ix - x0f, wy = iy - y0f;
            const int x0 = (int)x0f, y0 = (int)y0f;
            const int x1 = min(x0 + 1, 127), y1 = min(y0 + 1, 127);
            const int cx0 = s ? w : wm,  cx1 = s ? wp : w;
            const int cy0 = s ? h : hm,  cy1 = s ? hp : h;
            // Exact iff column-0/row-0 taps match; mismatched col-1/row-1
            // taps carry zero weight when wx/wy == 0.
            const bool ok = (x0 == cx0) && (wx == 0.0f || x1 == cx1)
                         && (y0 == cy0) && (wy == 0.0f || y1 == cy1);
            if (!ok) bad |= (1 << pos);
            WX[pos] = wx;
            WY[pos] = wy;
        }

        const int cbase = b * 64 + (g << 4);
        const float* pb = x + (cbase << 14);
        float* db = out + (cbase << 16) + (h << 9) + (w << 1);

        {   // fast path: 7 taps serve 4 outputs per channel (nested lerps)
            const float* p = pb;
            float* dst = db;
            #pragma unroll 2
            for (int cc = 0; cc < 16; cc++) {
                const float r00 = __ldg(p + rm + wm), r01 = __ldg(p + rm + w);
                const float r10 = __ldg(p + rc + wm), r11 = __ldg(p + rc + w);
                const float r12 = __ldg(p + rc + wp);
                const float r21 = __ldg(p + rp + w),  r22 = __ldg(p + rp + wp);
                float v[4];
                #pragma unroll
                for (int pos = 0; pos < 4; pos++) {
                    const int s = gg ? (pos >> 1) : (pos & 1);  // compile-time
                    const float t00 = s ? r11 : r00, t01 = s ? r12 : r01;
                    const float t10 = s ? r21 : r10, t11 = s ? r22 : r11;
                    const float h0 = fmaf(WX[pos], t01 - t00, t00);
                    const float h1 = fmaf(WX[pos], t11 - t10, t10);
                    v[pos] = fmaf(WY[pos], h1 - h0, h0);
                }
                stcs2(dst,       v[0], v[1]);   // row Y=2h
                stcs2(dst + 256, v[2], v[3]);   // row Y=2h+1
                p += HW;
                dst += 65536;
            }
        }

        if (bad) {  // cold exact repair (offset escaped predicted window)
            for (int pos = 0; pos < 4; pos++) {
                if (!(bad & (1 << pos))) continue;
                const int o = (g << 2) + pos;
                const float offx = offs[(o << 7) + w];
                const float offy = offs[((o + 16) << 7) + w];
                const float ix = clampf(fw + offx, 0.0f, 127.0f);
                const float iy = clampf(fh + offy, 0.0f, 127.0f);
                const float x0f = floorf(ix), y0f = floorf(iy);
                const float wx = ix - x0f, wy = iy - y0f;
                const int x0 = (int)x0f, y0 = (int)y0f;
                const int x1 = min(x0 + 1, 127), y1 = min(y0 + 1, 127);
                const float* p = pb;
                float* dst = db + (pos >> 1) * 256 + (pos & 1);
                for (int cc = 0; cc < 16; cc++) {
                    const float u00 = __ldg(p + (y0 << 7) + x0);
                    const float u01 = __ldg(p + (y0 << 7) + x1);
                    const float u10 = __ldg(p + (y1 << 7) + x0);
                    const float u11 = __ldg(p + (y1 << 7) + x1);
                    *dst = (1.0f - wy) * ((1.0f - wx) * u00 + wx * u01)
                         + wy * ((1.0f - wx) * u10 + wx * u11);
                    p += HW;
                    dst += 65536;
                }
            }
        }
    }
}

extern "C" void kernel_launch(void* const* d_in, const int* in_sizes, int n_in,
                              void* d_out, int out_size)
{
    const float* x     = (const float*)d_in[0];  // [16,64,128,128]
    const float* w_off = (const float*)d_in[1];  // [32,64]
    const float* b_off = (const float*)d_in[2];  // [32]
    float* out = (float*)d_out;                  // [16,64,256,256]

    dysample_fused<<<dim3(128, 16), 256>>>(x, w_off, b_off, out);
    (void)in_sizes; (void)n_in; (void)out_size;
}